// round 2
// baseline (speedup 1.0000x reference)
#include <cuda_runtime.h>
#include <cstdint>

#define T_BATCH 256
#define D_IN    784
#define M_      800
#define N_      8
#define K_      25
#define MN_     6400
#define NEG_INF (-3.402823466e38f)

// Scratch (allocation-free rule: __device__ globals)
__device__ float g_WbT[(size_t)MN_ * MN_];   // W_b transposed (163.84 MB)
__device__ float g_A[T_BATCH * M_];          // A[t][m] = W_a @ x_t + b_a
__device__ float g_WdT[M_ * D_IN];           // W_d transposed

// Monotone float<->uint order mapping (no NaNs in this workload)
__device__ __forceinline__ unsigned fmap(unsigned b) {
    return (b & 0x80000000u) ? ~b : (b | 0x80000000u);
}
__device__ __forceinline__ float funmap(unsigned u) {
    unsigned b = (u & 0x80000000u) ? (u & 0x7FFFFFFFu) : ~u;
    return __uint_as_float(b);
}

// ---------------------------------------------------------------------------
// W_b transpose: 6400x6400, 32x32 tiles
// ---------------------------------------------------------------------------
__global__ void transpose_wb(const float* __restrict__ W) {
    __shared__ float tile[32][33];
    int x  = blockIdx.x * 32 + threadIdx.x;   // column of W
    int y0 = blockIdx.y * 32;
#pragma unroll
    for (int i = threadIdx.y; i < 32; i += 8)
        tile[i][threadIdx.x] = W[(size_t)(y0 + i) * MN_ + x];
    __syncthreads();
    int x2 = blockIdx.y * 32 + threadIdx.x;   // row of W
    int y2 = blockIdx.x * 32;
#pragma unroll
    for (int i = threadIdx.y; i < 32; i += 8)
        g_WbT[(size_t)(y2 + i) * MN_ + x2] = tile[threadIdx.x][i];
}

// ---------------------------------------------------------------------------
// Fused prep: gemm_a (blocks 0..799) + transpose_wd (blocks 800..1424)
// 256 threads per block
// ---------------------------------------------------------------------------
__global__ void prep_kernel(const float* __restrict__ X, const float* __restrict__ Wa,
                            const float* __restrict__ ba, const float* __restrict__ Wd) {
    __shared__ float sh[32 * 33];
    int b = blockIdx.x;
    int tid = threadIdx.x;
    if (b < 800) {
        // A[t][m] = dot(X[t,:], Wa[m,:]) + ba[m]   (256x800, K=784)
        float (*xs)[17] = (float(*)[17])sh;
        float (*ws)[17] = (float(*)[17])(sh + 16 * 17);
        int bx = b % 50, by = b / 50;
        int tx = tid & 15, ty = tid >> 4;
        int m = bx * 16 + tx;
        int t = by * 16 + ty;
        float acc = 0.0f;
        for (int k0 = 0; k0 < D_IN; k0 += 16) {
            xs[ty][tx] = X[(by * 16 + ty) * D_IN + k0 + tx];
            ws[ty][tx] = Wa[(bx * 16 + ty) * D_IN + k0 + tx];
            __syncthreads();
#pragma unroll
            for (int k = 0; k < 16; ++k)
                acc = fmaf(xs[ty][k], ws[tx][k], acc);
            __syncthreads();
        }
        g_A[t * M_ + m] = acc + ba[m];
    } else {
        // W_d transpose (784, 800) -> (800, 784)
        float (*tile)[33] = (float(*)[33])sh;
        int r = b - 800;
        int g0 = (r % 25) * 32;
        int d0 = (r / 25) * 32;
        int tx = tid & 31, ty = tid >> 5;   // 32 x 8
#pragma unroll
        for (int i = ty; i < 32; i += 8) {
            int d = d0 + i, g = g0 + tx;
            if (d < D_IN && g < M_) tile[i][tx] = Wd[d * M_ + g];
        }
        __syncthreads();
#pragma unroll
        for (int i = ty; i < 32; i += 8) {
            int g = g0 + i, d = d0 + tx;
            if (g < M_ && d < D_IN) g_WdT[g * D_IN + d] = tile[tx][i];
        }
    }
}

// ---------------------------------------------------------------------------
// Main sequential scan: single CTA, 1024 threads, 3 barriers/step,
// software-pipelined speculative W-column + A-row prefetch.
// ---------------------------------------------------------------------------
__global__ void __launch_bounds__(1024, 1)
scan_kernel(const float* __restrict__ bb, const float* __restrict__ bd,
            float* __restrict__ out) {
    __shared__ __align__(16) float sigma_s[MN_];   // 25.6 KB
    __shared__ unsigned red_u[32], red_j[32], red_m[32];
    __shared__ float s_smin;
    __shared__ int   s_jstar;

    const int tid  = threadIdx.x;
    const int lane = tid & 31;
    const int wid  = tid >> 5;

    // Zero the x_b / phi / psi tail (d_out is poisoned); fenced from the
    // final tid==0 writes by the in-loop barriers.
    for (int i = tid; i < 3 * MN_; i += 1024) out[T_BATCH * D_IN + i] = 0.0f;

    // Per-thread constants across steps
    const int  j4a  = tid;                 // float4 chunk: j = 4*j4a .. +3
    const int  j4b  = tid + 1024;
    const bool hasb = (j4b < MN_ / 4);     // tid < 576
    const float4* bb4 = (const float4*)bb;
    const float4 bbA = bb4[j4a];
    const float4 bbB = hasb ? bb4[j4b] : make_float4(0.f, 0.f, 0.f, 0.f);
    const int aoffA = (4 * j4a) % M_;      // contiguous float4 within A row
    const int aoffB = hasb ? (4 * j4b) % M_ : 0;
    const float bdv = (tid < D_IN) ? bd[tid] : 0.0f;

    int   jp   = -1;     // active one-hot index of x_b / phi (-1 = zero vectors)
    float phiv = 0.0f;   // phi value at jp
    float4 cA = make_float4(0.f, 0.f, 0.f, 0.f);   // prefetched W column
    float4 cB = make_float4(0.f, 0.f, 0.f, 0.f);

    // Preload A row 0
    float4 aA = *(const float4*)(g_A + aoffA);
    float4 aB = hasb ? *(const float4*)(g_A + aoffB) : make_float4(0.f, 0.f, 0.f, 0.f);

    for (int t = 0; t < T_BATCH; ++t) {
        const bool use = (jp >= 0);
        // sigma = tile(a,N) + W_b[:,jp] + b_b   (reference add order)
        float sA[4], sB[4];
        sA[0] = (aA.x + (use ? cA.x : 0.f)) + bbA.x;
        sA[1] = (aA.y + (use ? cA.y : 0.f)) + bbA.y;
        sA[2] = (aA.z + (use ? cA.z : 0.f)) + bbA.z;
        sA[3] = (aA.w + (use ? cA.w : 0.f)) + bbA.w;
        ((float4*)sigma_s)[j4a] = make_float4(sA[0], sA[1], sA[2], sA[3]);
        if (hasb) {
            sB[0] = (aB.x + (use ? cB.x : 0.f)) + bbB.x;
            sB[1] = (aB.y + (use ? cB.y : 0.f)) + bbB.y;
            sB[2] = (aB.z + (use ? cB.z : 0.f)) + bbB.z;
            sB[3] = (aB.w + (use ? cB.w : 0.f)) + bbB.w;
            ((float4*)sigma_s)[j4b] = make_float4(sB[0], sB[1], sB[2], sB[3]);
        }

        // Local reductions: global min, argmax (excl jp, first-index ties),
        // and jp-excluded group maxes (group = 8 consecutive j; thread pair
        // (tid, tid^1) covers one group per chunk).
        unsigned um = 0xFFFFFFFFu;
        unsigned bu = 0u; unsigned bj = 0u;
        float gmA = NEG_INF, gmB = NEG_INF;
#pragma unroll
        for (int i = 0; i < 4; ++i) {
            unsigned u = fmap(__float_as_uint(sA[i]));
            um = min(um, u);
            int j = 4 * j4a + i;
            if (j != jp) {
                if (u > bu) { bu = u; bj = (unsigned)j; }
                gmA = fmaxf(gmA, sA[i]);
            }
        }
        if (hasb) {
#pragma unroll
            for (int i = 0; i < 4; ++i) {
                unsigned u = fmap(__float_as_uint(sB[i]));
                um = min(um, u);
                int j = 4 * j4b + i;
                if (j != jp) {
                    if (u > bu) { bu = u; bj = (unsigned)j; }
                    gmB = fmaxf(gmB, sB[i]);
                }
            }
        }
        // Pair exchange -> full (jp-excluded) group max in both lanes
        gmA = fmaxf(gmA, __shfl_xor_sync(0xFFFFFFFFu, gmA, 1));
        gmB = fmaxf(gmB, __shfl_xor_sync(0xFFFFFFFFu, gmB, 1));
        // Warp reductions via redux.sync
        unsigned wu = __reduce_max_sync(0xFFFFFFFFu, bu);
        unsigned wj = __reduce_min_sync(0xFFFFFFFFu, (bu == wu) ? bj : 0xFFFFFFFFu);
        unsigned wm = __reduce_min_sync(0xFFFFFFFFu, um);
        if (lane == 0) { red_u[wid] = wu; red_j[wid] = wj; red_m[wid] = wm; }
        __syncthreads();                                       // bar1
        if (wid == 0) {
            unsigned ru = red_u[lane], rj = red_j[lane], rm = red_m[lane];
            unsigned gu = __reduce_max_sync(0xFFFFFFFFu, ru);
            unsigned gj = __reduce_min_sync(0xFFFFFFFFu, (ru == gu) ? rj : 0xFFFFFFFFu);
            unsigned gm = __reduce_min_sync(0xFFFFFFFFu, rm);
            if (lane == 0) {
                float smin = funmap(gm);
                int M1 = (int)gj;
                int jstar = M1;
                if (jp >= 0) {
                    // pi is monotone in sigma except the single jp element
                    float v1 = (sigma_s[M1] - smin) + 1.0f;
                    float pv = (1.0f - phiv) * ((sigma_s[jp] - smin) + 1.0f);
                    if (pv > v1)       jstar = jp;
                    else if (pv == v1) jstar = (jp < M1) ? jp : M1;
                }
                s_smin  = smin;
                s_jstar = jstar;
            }
        }
        __syncthreads();                                       // bar2
        const float smin  = s_smin;
        const int   jstar = s_jstar;
        const int   gcol  = jstar >> 3;      // reshape-group (W_d column)
        const int   q     = jstar % M_;      // tile-group (m_lam mask)
        const int   gp    = (jp >= 0) ? (jp >> 3) : -1;

        // ---- Speculative prefetches: overlap lam/count/output phase ----
        {   // next W column (used iff yval > 0)
            const float4* wrow = (const float4*)(g_WbT + (size_t)jstar * MN_);
            cA = wrow[j4a];
            if (hasb) cB = wrow[j4b];
        }
        {   // next A row
            int tn = (t + 1 < T_BATCH) ? t + 1 : 0;
            const float* arow2 = g_A + tn * M_;
            aA = *(const float4*)(arow2 + aoffA);
            if (hasb) aB = *(const float4*)(arow2 + aoffB);
        }
        const float wd = (tid < D_IN) ? g_WdT[gcol * D_IN + tid] : 0.0f;
        const float sj = sigma_s[jstar];

        // lam[q] in pi space, computed redundantly by all threads
        // (8 broadcast LDS — conflict-free)
        float mq = NEG_INF;
#pragma unroll
        for (int n = 0; n < 8; ++n) {
            int j = 8 * q + n;
            float s = sigma_s[j];
            if (j != jp) mq = fmaxf(mq, s);
        }
        float lamq = (mq - smin) + 1.0f;
        if (q == gp) {
            float sc = (1.0f - phiv) * ((sigma_s[jp] - smin) + 1.0f);
            lamq = fmaxf(lamq, sc);
        }

        // Rank of q among lam values (stable top-k semantics):
        // even tid -> group tid/2 (chunk A); odd tid<576 -> group tid/2+512 (chunk B)
        int flag = 0;
        int m = -1; float gfull = NEG_INF;
        if ((tid & 1) == 0)      { m = tid >> 1;          gfull = gmA; }
        else if (tid < 576)      { m = (tid >> 1) + 512;  gfull = gmB; }
        if (m >= 0 && m != q) {
            float lm = (gfull - smin) + 1.0f;
            if (m == gp) {
                float sc = (1.0f - phiv) * ((sigma_s[jp] - smin) + 1.0f);
                lm = fmaxf(lm, sc);
            }
            flag = (lm > lamq) || (lm == lamq && m < q);
        }
        const int cnt = __syncthreads_count(flag);             // bar3

        const float tt   = tanhf(sj);
        const float yval = (cnt < K_) ? tt : 0.0f;             // m_lam gate
        const float gval = (yval > 0.0f) ? yval : 0.0f;        // relu'd group max

        if (tid < D_IN)
            out[t * D_IN + tid] = (gval > 0.0f) ? fmaf(wd, gval, bdv) : bdv;

        if (yval > 0.0f) { jp = jstar; phiv = yval; }
        else             { jp = -1;    phiv = 0.0f; }
    }

    // Final outputs: x_b (exactly one-hot 1.0), phi, psis[-1]
    if (tid == 0 && jp >= 0) {
        out[T_BATCH * D_IN + jp]           = 1.0f;   // x_b
        out[T_BATCH * D_IN + MN_ + jp]     = phiv;   // phi
        out[T_BATCH * D_IN + 2 * MN_ + jp] = phiv;   // psis[-1]
    }
}

// ---------------------------------------------------------------------------
extern "C" void kernel_launch(void* const* d_in, const int* in_sizes, int n_in,
                              void* d_out, int out_size) {
    const float* X  = (const float*)d_in[0];   // batch_x (256, 784)
    const float* Wa = (const float*)d_in[1];   // (800, 784)
    const float* ba = (const float*)d_in[2];   // (800,)
    const float* Wb = (const float*)d_in[3];   // (6400, 6400)
    const float* bb = (const float*)d_in[4];   // (6400,)
    const float* Wd = (const float*)d_in[5];   // (784, 800)
    const float* bd = (const float*)d_in[6];   // (784,)
    float* out = (float*)d_out;

    prep_kernel<<<1425, 256>>>(X, Wa, ba, Wd);
    transpose_wb<<<dim3(MN_ / 32, MN_ / 32), dim3(32, 8)>>>(Wb);
    scan_kernel<<<1, 1024>>>(bb, bd, out);
}

// round 5
// speedup vs baseline: 1.9923x; 1.9923x over previous
#include <cuda_runtime.h>
#include <cstdint>

#define T_BATCH 256
#define D_IN    784
#define M_      800
#define N_      8
#define K_      25
#define MN_     6400
#define NEG_INF (-3.402823466e38f)

// Scratch (allocation-free rule: __device__ globals)
__device__ float g_WbT[(size_t)MN_ * MN_];   // W_b transposed (163.84 MB)
__device__ float g_A[T_BATCH * M_];          // A[t][m] = W_a @ x_t + b_a
__device__ float g_WdT[M_ * D_IN];           // W_d transposed

// Monotone float<->uint order mapping (no NaNs in this workload)
__device__ __forceinline__ unsigned fmap(unsigned b) {
    return (b & 0x80000000u) ? ~b : (b | 0x80000000u);
}
__device__ __forceinline__ float funmap(unsigned u) {
    unsigned b = (u & 0x80000000u) ? (u & 0x7FFFFFFFu) : ~u;
    return __uint_as_float(b);
}

// ---------------------------------------------------------------------------
// Mega prep kernel, 256 threads/block:
//   blocks [0,200)      : A = X @ Wa^T + ba   (32x32 tiles, 2x2 micro-tiles)
//   blocks [200,825)    : W_d transpose (784,800) -> (800,784)
//   blocks [825,40825)  : W_b transpose 6400x6400 (DRAM-bound; overlaps GEMM)
// ---------------------------------------------------------------------------
#define GEMM_BLKS 200
#define WD_BLKS   625
#define WB_BASE   (GEMM_BLKS + WD_BLKS)
#define PREP_BLKS (WB_BASE + 200 * 200)

// GEMM smem tile stride: 36 floats = 144 bytes -> every row 16B-aligned
// (float4 LDS/STS legal), and != 32 to avoid full-warp bank conflicts.
#define TS 36

__global__ void __launch_bounds__(256)
prep_kernel(const float* __restrict__ X, const float* __restrict__ Wa,
            const float* __restrict__ ba, const float* __restrict__ Wd,
            const float* __restrict__ Wb) {
    __shared__ __align__(16) float sh[2 * 32 * TS];
    const int b = blockIdx.x;
    const int tid = threadIdx.x;

    if (b >= WB_BASE) {
        // ---- W_b transpose, 32x32 tile (scalar smem, stride 33) ----
        float (*tile)[33] = (float(*)[33])sh;
        int b2 = b - WB_BASE;
        int bx = b2 % 200, by = b2 / 200;
        int tx = tid & 31, ty = tid >> 5;         // 32 x 8
        int x = bx * 32 + tx;
        int y0 = by * 32;
#pragma unroll
        for (int i = ty; i < 32; i += 8)
            tile[i][tx] = Wb[(size_t)(y0 + i) * MN_ + x];
        __syncthreads();
        int x2 = by * 32 + tx;
        int y2 = bx * 32;
#pragma unroll
        for (int i = ty; i < 32; i += 8)
            g_WbT[(size_t)(y2 + i) * MN_ + x2] = tile[tx][i];
    } else if (b < GEMM_BLKS) {
        // ---- A[t][m] = dot(X[t,:], Wa[m,:]) + ba[m] ----
        float (*Xs)[TS] = (float(*)[TS])sh;             // [t][k]
        float (*Ws)[TS] = (float(*)[TS])(sh + 32 * TS); // [m][k]
        const int bm = b % 25, bt = b / 25;
        const int lrow = tid >> 3, lc4 = tid & 7;       // loader: 32 rows x 8 float4
        const int tx = tid & 15, ty = tid >> 4;         // compute: 2x2 per thread
        float c00 = 0.f, c01 = 0.f, c10 = 0.f, c11 = 0.f;
        for (int k0 = 0; k0 < D_IN; k0 += 32) {
            int kc = k0 + lc4 * 4;
            float4 xv = (kc + 3 < D_IN)
                ? *(const float4*)(X + (bt * 32 + lrow) * D_IN + kc)
                : make_float4(0.f, 0.f, 0.f, 0.f);
            float4 wv = (kc + 3 < D_IN)
                ? *(const float4*)(Wa + (bm * 32 + lrow) * D_IN + kc)
                : make_float4(0.f, 0.f, 0.f, 0.f);
            __syncthreads();
            *(float4*)&Xs[lrow][lc4 * 4] = xv;
            *(float4*)&Ws[lrow][lc4 * 4] = wv;
            __syncthreads();
#pragma unroll
            for (int k = 0; k < 32; k += 4) {
                float4 x0 = *(const float4*)&Xs[2 * ty][k];
                float4 x1 = *(const float4*)&Xs[2 * ty + 1][k];
                float4 w0 = *(const float4*)&Ws[2 * tx][k];
                float4 w1 = *(const float4*)&Ws[2 * tx + 1][k];
                c00 = fmaf(x0.x, w0.x, c00); c00 = fmaf(x0.y, w0.y, c00);
                c00 = fmaf(x0.z, w0.z, c00); c00 = fmaf(x0.w, w0.w, c00);
                c01 = fmaf(x0.x, w1.x, c01); c01 = fmaf(x0.y, w1.y, c01);
                c01 = fmaf(x0.z, w1.z, c01); c01 = fmaf(x0.w, w1.w, c01);
                c10 = fmaf(x1.x, w0.x, c10); c10 = fmaf(x1.y, w0.y, c10);
                c10 = fmaf(x1.z, w0.z, c10); c10 = fmaf(x1.w, w0.w, c10);
                c11 = fmaf(x1.x, w1.x, c11); c11 = fmaf(x1.y, w1.y, c11);
                c11 = fmaf(x1.z, w1.z, c11); c11 = fmaf(x1.w, w1.w, c11);
            }
        }
        int m0 = bm * 32 + 2 * tx, t0 = bt * 32 + 2 * ty;
        g_A[t0 * M_ + m0]           = c00 + ba[m0];
        g_A[t0 * M_ + m0 + 1]       = c01 + ba[m0 + 1];
        g_A[(t0 + 1) * M_ + m0]     = c10 + ba[m0];
        g_A[(t0 + 1) * M_ + m0 + 1] = c11 + ba[m0 + 1];
    } else {
        // ---- W_d transpose (784,800) -> (800,784) (scalar smem) ----
        float (*tile)[33] = (float(*)[33])sh;
        int r = b - GEMM_BLKS;
        int g0 = (r % 25) * 32;
        int d0 = (r / 25) * 32;
        int tx = tid & 31, ty = tid >> 5;
#pragma unroll
        for (int i = ty; i < 32; i += 8) {
            int d = d0 + i, g = g0 + tx;
            if (d < D_IN) tile[i][tx] = Wd[d * M_ + g];
        }
        __syncthreads();
#pragma unroll
        for (int i = ty; i < 32; i += 8) {
            int g = g0 + i, d = d0 + tx;
            if (d < D_IN) g_WdT[g * D_IN + d] = tile[tx][i];
        }
    }
}

// ---------------------------------------------------------------------------
// Main sequential scan: single CTA, 800 threads (thread m owns reshape group m,
// i.e. j = 8m..8m+7), 3 barriers/step, speculative W-column + A-row prefetch.
// ---------------------------------------------------------------------------
__global__ void __launch_bounds__(800, 1)
scan_kernel(const float* __restrict__ bb, const float* __restrict__ bd,
            float* __restrict__ out) {
    __shared__ __align__(16) float sigma_s[MN_];   // 25.6 KB
    __shared__ float lam_s[M_];                    // group max sigma excl jp
    __shared__ unsigned red_u[25], red_j[25], red_m[25];
    __shared__ float s_smin;
    __shared__ int   s_jstar;

    const int tid  = threadIdx.x;
    const int lane = tid & 31;
    const int wid  = tid >> 5;

    // Zero the x_b / phi / psi tail (d_out is poisoned)
    for (int i = tid; i < 3 * MN_; i += 800) out[T_BATCH * D_IN + i] = 0.0f;

    // Per-thread constants
    const float4* bb4 = (const float4*)bb;
    const float4 bbA = bb4[2 * tid];
    const float4 bbB = bb4[2 * tid + 1];
    const int aoff = 8 * (tid % 100);      // (8*tid) % 800, float4-aligned
    const float bdv = (tid < D_IN) ? bd[tid] : 0.0f;

    int   jp   = -1;     // active one-hot index of x_b / phi (-1 = zero vectors)
    float phiv = 0.0f;   // phi value at jp
    float4 cA = make_float4(0.f, 0.f, 0.f, 0.f);   // prefetched W column
    float4 cB = make_float4(0.f, 0.f, 0.f, 0.f);
    float4 aA = *(const float4*)(g_A + aoff);       // prefetched A row
    float4 aB = *(const float4*)(g_A + aoff + 4);

    for (int t = 0; t < T_BATCH; ++t) {
        const bool use = (jp >= 0);
        // sigma = tile(a,N) + W_b[:,jp] + b_b   (reference add order)
        float s[8];
        s[0] = (aA.x + (use ? cA.x : 0.f)) + bbA.x;
        s[1] = (aA.y + (use ? cA.y : 0.f)) + bbA.y;
        s[2] = (aA.z + (use ? cA.z : 0.f)) + bbA.z;
        s[3] = (aA.w + (use ? cA.w : 0.f)) + bbA.w;
        s[4] = (aB.x + (use ? cB.x : 0.f)) + bbB.x;
        s[5] = (aB.y + (use ? cB.y : 0.f)) + bbB.y;
        s[6] = (aB.z + (use ? cB.z : 0.f)) + bbB.z;
        s[7] = (aB.w + (use ? cB.w : 0.f)) + bbB.w;
        ((float4*)sigma_s)[2 * tid]     = make_float4(s[0], s[1], s[2], s[3]);
        ((float4*)sigma_s)[2 * tid + 1] = make_float4(s[4], s[5], s[6], s[7]);

        // Thread-local reductions over the owned group of 8:
        // global min, argmax excl jp (first-index ties), group max excl jp (lam)
        unsigned um = 0xFFFFFFFFu, bu = 0u, bj = 0u;
        float gm = NEG_INF;
#pragma unroll
        for (int i = 0; i < 8; ++i) {
            unsigned u = fmap(__float_as_uint(s[i]));
            um = min(um, u);
            int j = 8 * tid + i;
            if (j != jp) {
                if (u > bu) { bu = u; bj = (unsigned)j; }
                gm = fmaxf(gm, s[i]);
            }
        }
        lam_s[tid] = gm;
        // Warp reductions (redux.sync)
        unsigned wu = __reduce_max_sync(0xFFFFFFFFu, bu);
        unsigned wj = __reduce_min_sync(0xFFFFFFFFu, (bu == wu) ? bj : 0xFFFFFFFFu);
        unsigned wm = __reduce_min_sync(0xFFFFFFFFu, um);
        if (lane == 0) { red_u[wid] = wu; red_j[wid] = wj; red_m[wid] = wm; }
        __syncthreads();                                       // bar1
        if (wid == 0) {
            const bool v = (lane < 25);
            unsigned ru = v ? red_u[lane] : 0u;
            unsigned rj = v ? red_j[lane] : 0xFFFFFFFFu;
            unsigned rm = v ? red_m[lane] : 0xFFFFFFFFu;
            unsigned gu  = __reduce_max_sync(0xFFFFFFFFu, ru);
            unsigned gj  = __reduce_min_sync(0xFFFFFFFFu, (ru == gu) ? rj : 0xFFFFFFFFu);
            unsigned gmn = __reduce_min_sync(0xFFFFFFFFu, rm);
            if (lane == 0) {
                float smin = funmap(gmn);
                int M1 = (int)gj;
                int jstar = M1;
                if (jp >= 0) {
                    // pi is monotone in sigma except the single jp element
                    float v1 = (sigma_s[M1] - smin) + 1.0f;
                    float pv = (1.0f - phiv) * ((sigma_s[jp] - smin) + 1.0f);
                    if (pv > v1)       jstar = jp;
                    else if (pv == v1) jstar = (jp < M1) ? jp : M1;
                }
                s_smin  = smin;
                s_jstar = jstar;
            }
        }
        __syncthreads();                                       // bar2
        const float smin  = s_smin;
        const int   jstar = s_jstar;
        const int   q     = jstar % M_;      // lam-group gating index (tile)
        const int   gcol  = jstar >> 3;      // reshape group (W_d column)
        const int   gp    = (jp >= 0) ? (jp >> 3) : -1;

        // ---- Speculative prefetches (overlap lam/count/output phase) ----
        {
            const float4* wrow = (const float4*)(g_WbT + (size_t)jstar * MN_);
            cA = wrow[2 * tid];
            cB = wrow[2 * tid + 1];
        }
        {
            int tn = (t + 1 < T_BATCH) ? t + 1 : 0;
            const float* ar = g_A + tn * M_;
            aA = *(const float4*)(ar + aoff);
            aB = *(const float4*)(ar + aoff + 4);
        }
        const float wd = (tid < D_IN) ? g_WdT[gcol * D_IN + tid] : 0.0f;
        const float sj = sigma_s[jstar];

        // lam[q] and this thread's lam, in pi space (exact reference formula)
        float pvp = 0.0f;
        if (jp >= 0) pvp = (1.0f - phiv) * ((sigma_s[jp] - smin) + 1.0f);
        float lamq = (lam_s[q] - smin) + 1.0f;
        if (q == gp) lamq = fmaxf(lamq, pvp);
        int flag = 0;
        if (tid != q) {
            float lm = (gm - smin) + 1.0f;
            if (tid == gp) lm = fmaxf(lm, pvp);
            flag = (lm > lamq) || (lm == lamq && tid < q);
        }
        const int cnt = __syncthreads_count(flag);             // bar3

        const float tt   = tanhf(sj);
        const float yval = (cnt < K_) ? tt : 0.0f;             // m_lam gate
        const float gval = (yval > 0.0f) ? yval : 0.0f;        // relu'd group max

        if (tid < D_IN)
            out[t * D_IN + tid] = (gval > 0.0f) ? fmaf(wd, gval, bdv) : bdv;

        if (yval > 0.0f) { jp = jstar; phiv = yval; }
        else             { jp = -1;    phiv = 0.0f; }
    }

    // Final outputs: x_b (exactly one-hot 1.0), phi, psis[-1]
    if (tid == 0 && jp >= 0) {
        out[T_BATCH * D_IN + jp]           = 1.0f;   // x_b
        out[T_BATCH * D_IN + MN_ + jp]     = phiv;   // phi
        out[T_BATCH * D_IN + 2 * MN_ + jp] = phiv;   // psis[-1]
    }
}

// ---------------------------------------------------------------------------
extern "C" void kernel_launch(void* const* d_in, const int* in_sizes, int n_in,
                              void* d_out, int out_size) {
    const float* X  = (const float*)d_in[0];   // batch_x (256, 784)
    const float* Wa = (const float*)d_in[1];   // (800, 784)
    const float* ba = (const float*)d_in[2];   // (800,)
    const float* Wb = (const float*)d_in[3];   // (6400, 6400)
    const float* bb = (const float*)d_in[4];   // (6400,)
    const float* Wd = (const float*)d_in[5];   // (784, 800)
    const float* bd = (const float*)d_in[6];   // (784,)
    float* out = (float*)d_out;

    prep_kernel<<<PREP_BLKS, 256>>>(X, Wa, ba, Wd, Wb);
    scan_kernel<<<1, 800>>>(bb, bd, out);
}